// round 7
// baseline (speedup 1.0000x reference)
#include <cuda_runtime.h>
#include <cuda_bf16.h>
#include <math.h>

// MixtralRouterLoss: gate_logits [T, 8] fp32 -> scalar fp32
//   probs = softmax(logits, -1)
//   top-2 experts per token (monotone: same as top-2 of logits)
//   loss = 0.02 * 8 * sum_e (mean_prob[e] * (top2_count[e]/T))
// The [K,E] sum collapses: tokens_per_expert summed over K == top2_count[e]/T,
// and router_prob_per_expert[e] is independent of k.

#define GRID  2048
#define BLOCK 256
#define NE    8

// Per-block partials: [GRID][16] = 8 prob sums + 8 top2 counts.
// Every slot is overwritten by every launch -> no zeroing pass needed.
__device__ float g_partials[GRID * 16];

__device__ __forceinline__ void row_accum(const float v[NE],
                                          float psum[NE], float cnt[NE])
{
    // stable softmax over 8 lanes
    float m = v[0];
#pragma unroll
    for (int i = 1; i < NE; i++) m = fmaxf(m, v[i]);

    float e[NE];
    float s = 0.0f;
#pragma unroll
    for (int i = 0; i < NE; i++) { e[i] = __expf(v[i] - m); s += e[i]; }
    float inv = 1.0f / s;

#pragma unroll
    for (int i = 0; i < NE; i++) psum[i] += e[i] * inv;

    // top-2 indices by logit (== top-2 by softmax; same first-index tie rule)
    int i1 = 0; float m1 = v[0];
#pragma unroll
    for (int i = 1; i < NE; i++) { if (v[i] > m1) { m1 = v[i]; i1 = i; } }
    int i2 = -1; float m2 = -INFINITY;
#pragma unroll
    for (int i = 0; i < NE; i++) { if (i != i1 && v[i] > m2) { m2 = v[i]; i2 = i; } }

    cnt[i1] += 1.0f;
    cnt[i2] += 1.0f;
}

__global__ __launch_bounds__(BLOCK) void router_main_kernel(
    const float* __restrict__ logits, long long T)
{
    float psum[NE];
    float cnt[NE];
#pragma unroll
    for (int i = 0; i < NE; i++) { psum[i] = 0.0f; cnt[i] = 0.0f; }

    long long tid    = (long long)blockIdx.x * BLOCK + threadIdx.x;
    long long stride = (long long)GRID * BLOCK;

    // 2 rows per trip: 4 independent streaming LDG.128s batched before any
    // math (MLP=4). __ldcs: data is read exactly once -> evict-first, no L2
    // allocate churn.
    long long r = tid;
    for (; r + stride < T; r += 2 * stride) {
        const float4* p0 = reinterpret_cast<const float4*>(logits + r * NE);
        const float4* p1 = reinterpret_cast<const float4*>(logits + (r + stride) * NE);
        float4 a0 = __ldcs(p0 + 0);
        float4 b0 = __ldcs(p0 + 1);
        float4 a1 = __ldcs(p1 + 0);
        float4 b1 = __ldcs(p1 + 1);

        float v0[NE] = {a0.x, a0.y, a0.z, a0.w, b0.x, b0.y, b0.z, b0.w};
        float v1[NE] = {a1.x, a1.y, a1.z, a1.w, b1.x, b1.y, b1.z, b1.w};

        row_accum(v0, psum, cnt);
        row_accum(v1, psum, cnt);
    }
    if (r < T) {
        const float4* p = reinterpret_cast<const float4*>(logits + r * NE);
        float4 a = __ldcs(p + 0);
        float4 b = __ldcs(p + 1);
        float v[NE] = {a.x, a.y, a.z, a.w, b.x, b.y, b.z, b.w};
        row_accum(v, psum, cnt);
    }

    // warp-level tree reduce of all 16 accumulators
#pragma unroll
    for (int i = 0; i < NE; i++) {
#pragma unroll
        for (int off = 16; off > 0; off >>= 1) {
            psum[i] += __shfl_down_sync(0xFFFFFFFFu, psum[i], off);
            cnt[i]  += __shfl_down_sync(0xFFFFFFFFu, cnt[i],  off);
        }
    }

    __shared__ float sh[16];
    if (threadIdx.x < 16) sh[threadIdx.x] = 0.0f;
    __syncthreads();

    if ((threadIdx.x & 31) == 0) {
#pragma unroll
        for (int i = 0; i < NE; i++) {
            atomicAdd(&sh[i],      psum[i]);
            atomicAdd(&sh[NE + i], cnt[i]);
        }
    }
    __syncthreads();

    if (threadIdx.x < 16)
        g_partials[blockIdx.x * 16 + threadIdx.x] = sh[threadIdx.x];
}

// One block, 16 warps: warp w reduces column w across all GRID block-partials.
__global__ __launch_bounds__(512) void router_finalize_kernel(
    float* __restrict__ out, long long T)
{
    int w    = threadIdx.x >> 5;   // 0..15 -> column
    int lane = threadIdx.x & 31;

    float s = 0.0f;
    for (int b = lane; b < GRID; b += 32)
        s += g_partials[b * 16 + w];

#pragma unroll
    for (int off = 16; off > 0; off >>= 1)
        s += __shfl_down_sync(0xFFFFFFFFu, s, off);

    __shared__ float sh[16];
    if (lane == 0) sh[w] = s;
    __syncthreads();

    if (threadIdx.x == 0) {
        float invT = 1.0f / (float)T;
        float loss = 0.0f;
#pragma unroll
        for (int e = 0; e < NE; e++)
            loss += (sh[e] * invT) * (sh[NE + e] * invT);
        out[0] = 0.02f * 8.0f * loss;
    }
}

extern "C" void kernel_launch(void* const* d_in, const int* in_sizes, int n_in,
                              void* d_out, int out_size)
{
    const float* logits = (const float*)d_in[0];
    long long T = (long long)in_sizes[0] / NE;
    float* out = (float*)d_out;

    router_main_kernel<<<GRID, BLOCK>>>(logits, T);
    router_finalize_kernel<<<1, 512>>>(out, T);
}

// round 11
// speedup vs baseline: 1.0576x; 1.0576x over previous
#include <cuda_runtime.h>
#include <cuda_bf16.h>
#include <math.h>

// MixtralRouterLoss: gate_logits [T, 8] fp32 -> scalar fp32
//   probs = softmax(logits, -1); top-2 experts per token (monotone: top-2 of
//   logits); loss = 0.02 * 8 * sum_e (mean_prob[e] * (top2_count[e]/T)).
// [K,E] sum collapses: tokens_per_expert summed over K == top2_count[e]/T.

#define GRID  2048
#define BLOCK 256
#define NE    8

// TRANSPOSED partials: [16][GRID] = column c (8 prob sums, 8 counts) laid out
// contiguously over blocks -> finalize reads are fully coalesced.
// Every slot overwritten every launch -> no zeroing pass, graph-safe.
__device__ float g_partials[16 * GRID];

__device__ __forceinline__ void row_accum(const float v[NE],
                                          float psum[NE], float cnt[NE])
{
    // stable softmax over 8 lanes
    float m = v[0];
#pragma unroll
    for (int i = 1; i < NE; i++) m = fmaxf(m, v[i]);

    float e[NE];
    float s = 0.0f;
#pragma unroll
    for (int i = 0; i < NE; i++) { e[i] = __expf(v[i] - m); s += e[i]; }
    float inv = 1.0f / s;

#pragma unroll
    for (int i = 0; i < NE; i++) psum[i] += e[i] * inv;

    // top-2 indices by logit (== top-2 by softmax; first-index tie rule)
    int i1 = 0; float m1 = v[0];
#pragma unroll
    for (int i = 1; i < NE; i++) { if (v[i] > m1) { m1 = v[i]; i1 = i; } }
    int i2 = -1; float m2 = -INFINITY;
#pragma unroll
    for (int i = 0; i < NE; i++) { if (i != i1 && v[i] > m2) { m2 = v[i]; i2 = i; } }

    cnt[i1] += 1.0f;
    cnt[i2] += 1.0f;
}

__device__ __forceinline__ void load_row(const float* __restrict__ base,
                                         long long r, float4& a, float4& b)
{
    const float4* p = reinterpret_cast<const float4*>(base + r * NE);
    a = __ldcs(p + 0);
    b = __ldcs(p + 1);
}

__global__ __launch_bounds__(BLOCK) void router_main_kernel(
    const float* __restrict__ logits, long long T)
{
    float psum[NE];
    float cnt[NE];
#pragma unroll
    for (int i = 0; i < NE; i++) { psum[i] = 0.0f; cnt[i] = 0.0f; }

    long long tid    = (long long)blockIdx.x * BLOCK + threadIdx.x;
    long long stride = (long long)GRID * BLOCK;

    // 4 rows per trip: 8 independent streaming LDG.128s batched before any
    // math -> warp MLP=8. For T=4194304 this is exactly 2 trips, no tail.
    long long r = tid;
    for (; r + 3 * stride < T; r += 4 * stride) {
        float4 a0, b0, a1, b1, a2, b2, a3, b3;
        load_row(logits, r,              a0, b0);
        load_row(logits, r + stride,     a1, b1);
        load_row(logits, r + 2 * stride, a2, b2);
        load_row(logits, r + 3 * stride, a3, b3);

        float v0[NE] = {a0.x, a0.y, a0.z, a0.w, b0.x, b0.y, b0.z, b0.w};
        float v1[NE] = {a1.x, a1.y, a1.z, a1.w, b1.x, b1.y, b1.z, b1.w};
        float v2[NE] = {a2.x, a2.y, a2.z, a2.w, b2.x, b2.y, b2.z, b2.w};
        float v3[NE] = {a3.x, a3.y, a3.z, a3.w, b3.x, b3.y, b3.z, b3.w};

        row_accum(v0, psum, cnt);
        row_accum(v1, psum, cnt);
        row_accum(v2, psum, cnt);
        row_accum(v3, psum, cnt);
    }
    for (; r < T; r += stride) {
        float4 a, b;
        load_row(logits, r, a, b);
        float v[NE] = {a.x, a.y, a.z, a.w, b.x, b.y, b.z, b.w};
        row_accum(v, psum, cnt);
    }

    // warp-level tree reduce of all 16 accumulators
#pragma unroll
    for (int i = 0; i < NE; i++) {
#pragma unroll
        for (int off = 16; off > 0; off >>= 1) {
            psum[i] += __shfl_down_sync(0xFFFFFFFFu, psum[i], off);
            cnt[i]  += __shfl_down_sync(0xFFFFFFFFu, cnt[i],  off);
        }
    }

    __shared__ float sh[16];
    if (threadIdx.x < 16) sh[threadIdx.x] = 0.0f;
    __syncthreads();

    if ((threadIdx.x & 31) == 0) {
#pragma unroll
        for (int i = 0; i < NE; i++) {
            atomicAdd(&sh[i],      psum[i]);
            atomicAdd(&sh[NE + i], cnt[i]);
        }
    }
    __syncthreads();

    // transposed store: accumulator c for this block -> g_partials[c*GRID + bid]
    if (threadIdx.x < 16)
        g_partials[threadIdx.x * GRID + blockIdx.x] = sh[threadIdx.x];
}

// One block, 16 warps: warp w reduces row w of the transposed partials with
// fully coalesced float4 loads (GRID/(32*4) = 16 iterations per warp).
__global__ __launch_bounds__(512) void router_finalize_kernel(
    float* __restrict__ out, long long T)
{
    int w    = threadIdx.x >> 5;   // 0..15 -> accumulator row
    int lane = threadIdx.x & 31;

    const float4* row = reinterpret_cast<const float4*>(&g_partials[w * GRID]);
    float s = 0.0f;
#pragma unroll 4
    for (int i = lane; i < GRID / 4; i += 32) {
        float4 v = row[i];
        s += (v.x + v.y) + (v.z + v.w);
    }

#pragma unroll
    for (int off = 16; off > 0; off >>= 1)
        s += __shfl_down_sync(0xFFFFFFFFu, s, off);

    __shared__ float sh[16];
    if (lane == 0) sh[w] = s;
    __syncthreads();

    if (threadIdx.x == 0) {
        float invT = 1.0f / (float)T;
        float loss = 0.0f;
#pragma unroll
        for (int e = 0; e < NE; e++)
            loss += (sh[e] * invT) * (sh[NE + e] * invT);
        out[0] = 0.02f * 8.0f * loss;
    }
}

extern "C" void kernel_launch(void* const* d_in, const int* in_sizes, int n_in,
                              void* d_out, int out_size)
{
    const float* logits = (const float*)d_in[0];
    long long T = (long long)in_sizes[0] / NE;
    float* out = (float*)d_out;

    router_main_kernel<<<GRID, BLOCK>>>(logits, T);
    router_finalize_kernel<<<1, 512>>>(out, T);
}

// round 15
// speedup vs baseline: 1.0860x; 1.0269x over previous
#include <cuda_runtime.h>
#include <cuda_bf16.h>
#include <math.h>

// MixtralRouterLoss: gate_logits [T, 8] fp32 -> scalar fp32
//   probs = softmax(logits, -1); top-2 experts per token (monotone: top-2 of
//   logits); loss = 0.02 * 8 * sum_e (mean_prob[e] * (top2_count[e]/T)).
// [K,E] sum collapses: tokens_per_expert summed over K == top2_count[e]/T.
//
// Single fused kernel; 2 rows/trip (MLP_p1=4: R7-measured faster than the
// 8-batched variant -- front-batched LDG.128s drive cross-CTA L1tex spread).
// Last block (ticket pattern) reduces the transposed partials.

#define GRID  2048
#define BLOCK 256
#define NE    8

// TRANSPOSED partials: [16][GRID]; every slot overwritten every launch.
__device__ float g_partials[16 * GRID];
// Ticket counter; zero-init at load, reset to 0 by the last block each launch.
__device__ unsigned int g_ticket;

__device__ __forceinline__ void row_accum(const float v[NE],
                                          float psum[NE], float cnt[NE])
{
    // stable softmax over 8 lanes
    float m = v[0];
#pragma unroll
    for (int i = 1; i < NE; i++) m = fmaxf(m, v[i]);

    float e[NE];
    float s = 0.0f;
#pragma unroll
    for (int i = 0; i < NE; i++) { e[i] = __expf(v[i] - m); s += e[i]; }
    float inv = 1.0f / s;

#pragma unroll
    for (int i = 0; i < NE; i++) psum[i] += e[i] * inv;

    // top-2 indices by logit (== top-2 by softmax; first-index tie rule)
    int i1 = 0; float m1 = v[0];
#pragma unroll
    for (int i = 1; i < NE; i++) { if (v[i] > m1) { m1 = v[i]; i1 = i; } }
    int i2 = -1; float m2 = -INFINITY;
#pragma unroll
    for (int i = 0; i < NE; i++) { if (i != i1 && v[i] > m2) { m2 = v[i]; i2 = i; } }

    cnt[i1] += 1.0f;
    cnt[i2] += 1.0f;
}

__device__ __forceinline__ void load_row(const float* __restrict__ base,
                                         long long r, float4& a, float4& b)
{
    const float4* p = reinterpret_cast<const float4*>(base + r * NE);
    a = __ldcs(p + 0);
    b = __ldcs(p + 1);
}

__global__ __launch_bounds__(BLOCK) void router_fused_kernel(
    const float* __restrict__ logits, float* __restrict__ out, long long T)
{
    float psum[NE];
    float cnt[NE];
#pragma unroll
    for (int i = 0; i < NE; i++) { psum[i] = 0.0f; cnt[i] = 0.0f; }

    long long tid    = (long long)blockIdx.x * BLOCK + threadIdx.x;
    long long stride = (long long)GRID * BLOCK;

    // 2 rows per trip: 4 independent streaming LDG.128s batched (MLP_p1=4,
    // at the cross-CTA L1tex spread knee). T=4194304 -> exactly 4 trips/thread.
    long long r = tid;
    for (; r + stride < T; r += 2 * stride) {
        float4 a0, b0, a1, b1;
        load_row(logits, r,          a0, b0);
        load_row(logits, r + stride, a1, b1);

        float v0[NE] = {a0.x, a0.y, a0.z, a0.w, b0.x, b0.y, b0.z, b0.w};
        float v1[NE] = {a1.x, a1.y, a1.z, a1.w, b1.x, b1.y, b1.z, b1.w};

        row_accum(v0, psum, cnt);
        row_accum(v1, psum, cnt);
    }
    if (r < T) {
        float4 a, b;
        load_row(logits, r, a, b);
        float v[NE] = {a.x, a.y, a.z, a.w, b.x, b.y, b.z, b.w};
        row_accum(v, psum, cnt);
    }

    // warp-level tree reduce of all 16 accumulators
#pragma unroll
    for (int i = 0; i < NE; i++) {
#pragma unroll
        for (int off = 16; off > 0; off >>= 1) {
            psum[i] += __shfl_down_sync(0xFFFFFFFFu, psum[i], off);
            cnt[i]  += __shfl_down_sync(0xFFFFFFFFu, cnt[i],  off);
        }
    }

    __shared__ float sh[16];
    if (threadIdx.x < 16) sh[threadIdx.x] = 0.0f;
    __syncthreads();

    if ((threadIdx.x & 31) == 0) {
#pragma unroll
        for (int i = 0; i < NE; i++) {
            atomicAdd(&sh[i],      psum[i]);
            atomicAdd(&sh[NE + i], cnt[i]);
        }
    }
    __syncthreads();

    // transposed store: accumulator c for this block -> g_partials[c*GRID + bid]
    if (threadIdx.x < 16)
        g_partials[threadIdx.x * GRID + blockIdx.x] = sh[threadIdx.x];

    // ---- last-block finalize (threadFenceReduction pattern) ----
    __threadfence();
    __shared__ bool is_last;
    if (threadIdx.x == 0) {
        unsigned int t = atomicAdd(&g_ticket, 1u);
        is_last = (t == (unsigned int)(GRID - 1));
        if (is_last) g_ticket = 0u;   // reset for the next launch
    }
    __syncthreads();
    if (!is_last) return;

    // 8 warps; warp w reduces transposed rows 2w and 2w+1 (coalesced float4).
    int w    = threadIdx.x >> 5;
    int lane = threadIdx.x & 31;
    __shared__ float fin[16];

#pragma unroll
    for (int k = 0; k < 2; k++) {
        int rowi = w * 2 + k;
        const float4* row = reinterpret_cast<const float4*>(&g_partials[rowi * GRID]);
        float s = 0.0f;
#pragma unroll 4
        for (int i = lane; i < GRID / 4; i += 32) {
            float4 v = row[i];
            s += (v.x + v.y) + (v.z + v.w);
        }
#pragma unroll
        for (int off = 16; off > 0; off >>= 1)
            s += __shfl_down_sync(0xFFFFFFFFu, s, off);
        if (lane == 0) fin[rowi] = s;
    }
    __syncthreads();

    if (threadIdx.x == 0) {
        float invT = 1.0f / (float)T;
        float loss = 0.0f;
#pragma unroll
        for (int e = 0; e < NE; e++)
            loss += (fin[e] * invT) * (fin[NE + e] * invT);
        out[0] = 0.02f * 8.0f * loss;
    }
}

extern "C" void kernel_launch(void* const* d_in, const int* in_sizes, int n_in,
                              void* d_out, int out_size)
{
    const float* logits = (const float*)d_in[0];
    long long T = (long long)in_sizes[0] / NE;
    float* out = (float*)d_out;

    router_fused_kernel<<<GRID, BLOCK>>>(logits, out, T);
}

// round 17
// speedup vs baseline: 1.3268x; 1.2217x over previous
#include <cuda_runtime.h>
#include <cuda_bf16.h>
#include <math.h>

// MixtralRouterLoss: gate_logits [T, 8] fp32 -> scalar fp32
//   probs = softmax(logits, -1); top-2 experts per token;
//   loss = 0.02 * 8 * sum_e (mean_prob[e] * (top2_count[e]/T)).
//
// R15 profile: ALU 52% / issue 65% / DRAM 38% -> issue-bound from dynamic
// register indexing (cnt[i1]+=1 select chains) + index-tracking scans.
// This version is fully branch-free and index-free:
//   m1 = row max (softmax + top1), m2 = max of (v masked at m1),
//   cnt[i] += (v[i] >= m2)  -- counts exactly the top-2 lanes.

#define GRID  2048
#define BLOCK 256
#define NE    8

// TRANSPOSED partials: [16][GRID]; every slot overwritten every launch.
__device__ float g_partials[16 * GRID];
// Ticket counter; zero-init at load, reset to 0 by the last block each launch.
__device__ unsigned int g_ticket;

__device__ __forceinline__ void row_accum(const float v[NE],
                                          float psum[NE], float cnt[NE])
{
    const float L2E = 1.4426950408889634f;

    // row max, 7-op tree (feeds both softmax and top-2)
    float a  = fmaxf(v[0], v[1]);
    float b  = fmaxf(v[2], v[3]);
    float c  = fmaxf(v[4], v[5]);
    float d  = fmaxf(v[6], v[7]);
    float m1 = fmaxf(fmaxf(a, b), fmaxf(c, d));

    // exp2(v*log2e - m1*log2e): one FFMA + one MUFU.EX2 per lane
    float mb = m1 * L2E;
    float e[NE];
#pragma unroll
    for (int i = 0; i < NE; i++) e[i] = exp2f(fmaf(v[i], L2E, -mb));

    float s = ((e[0] + e[1]) + (e[2] + e[3])) + ((e[4] + e[5]) + (e[6] + e[7]));
    float inv = __fdividef(1.0f, s);   // single MUFU.RCP
#pragma unroll
    for (int i = 0; i < NE; i++) psum[i] = fmaf(e[i], inv, psum[i]);

    // second max: mask out the max lane(s), re-max (branch-free)
    float t[NE];
#pragma unroll
    for (int i = 0; i < NE; i++) t[i] = (v[i] == m1) ? -INFINITY : v[i];
    float ta = fmaxf(t[0], t[1]);
    float tb = fmaxf(t[2], t[3]);
    float tc = fmaxf(t[4], t[5]);
    float td = fmaxf(t[6], t[7]);
    float m2 = fmaxf(fmaxf(ta, tb), fmaxf(tc, td));

    // count top-2 lanes: v >= m2 holds exactly for top1 and top2
#pragma unroll
    for (int i = 0; i < NE; i++) cnt[i] += (v[i] >= m2) ? 1.0f : 0.0f;
}

__device__ __forceinline__ void load_row(const float* __restrict__ base,
                                         long long r, float4& a, float4& b)
{
    const float4* p = reinterpret_cast<const float4*>(base + r * NE);
    a = __ldcs(p + 0);
    b = __ldcs(p + 1);
}

__global__ __launch_bounds__(BLOCK) void router_fused_kernel(
    const float* __restrict__ logits, float* __restrict__ out, long long T)
{
    float psum[NE];
    float cnt[NE];
#pragma unroll
    for (int i = 0; i < NE; i++) { psum[i] = 0.0f; cnt[i] = 0.0f; }

    long long tid    = (long long)blockIdx.x * BLOCK + threadIdx.x;
    long long stride = (long long)GRID * BLOCK;

    // 2 rows per trip (MLP_p1=4). T=4194304 -> exactly 4 trips/thread.
    long long r = tid;
    for (; r + stride < T; r += 2 * stride) {
        float4 a0, b0, a1, b1;
        load_row(logits, r,          a0, b0);
        load_row(logits, r + stride, a1, b1);

        float v0[NE] = {a0.x, a0.y, a0.z, a0.w, b0.x, b0.y, b0.z, b0.w};
        float v1[NE] = {a1.x, a1.y, a1.z, a1.w, b1.x, b1.y, b1.z, b1.w};

        row_accum(v0, psum, cnt);
        row_accum(v1, psum, cnt);
    }
    if (r < T) {
        float4 a, b;
        load_row(logits, r, a, b);
        float v[NE] = {a.x, a.y, a.z, a.w, b.x, b.y, b.z, b.w};
        row_accum(v, psum, cnt);
    }

    // warp-level tree reduce of all 16 accumulators
#pragma unroll
    for (int i = 0; i < NE; i++) {
#pragma unroll
        for (int off = 16; off > 0; off >>= 1) {
            psum[i] += __shfl_down_sync(0xFFFFFFFFu, psum[i], off);
            cnt[i]  += __shfl_down_sync(0xFFFFFFFFu, cnt[i],  off);
        }
    }

    __shared__ float sh[16];
    if (threadIdx.x < 16) sh[threadIdx.x] = 0.0f;
    __syncthreads();

    if ((threadIdx.x & 31) == 0) {
#pragma unroll
        for (int i = 0; i < NE; i++) {
            atomicAdd(&sh[i],      psum[i]);
            atomicAdd(&sh[NE + i], cnt[i]);
        }
    }
    __syncthreads();

    // transposed store: accumulator c for this block -> g_partials[c*GRID + bid]
    if (threadIdx.x < 16)
        g_partials[threadIdx.x * GRID + blockIdx.x] = sh[threadIdx.x];

    // ---- last-block finalize (threadFenceReduction pattern) ----
    __threadfence();
    __shared__ bool is_last;
    if (threadIdx.x == 0) {
        unsigned int t = atomicAdd(&g_ticket, 1u);
        is_last = (t == (unsigned int)(GRID - 1));
        if (is_last) g_ticket = 0u;   // reset for the next launch
    }
    __syncthreads();
    if (!is_last) return;

    // 8 warps; warp w reduces transposed rows 2w and 2w+1 (coalesced float4).
    int w    = threadIdx.x >> 5;
    int lane = threadIdx.x & 31;
    __shared__ float fin[16];

#pragma unroll
    for (int k = 0; k < 2; k++) {
        int rowi = w * 2 + k;
        const float4* row = reinterpret_cast<const float4*>(&g_partials[rowi * GRID]);
        float s = 0.0f;
#pragma unroll 4
        for (int i = lane; i < GRID / 4; i += 32) {
            float4 v = row[i];
            s += (v.x + v.y) + (v.z + v.w);
        }
#pragma unroll
        for (int off = 16; off > 0; off >>= 1)
            s += __shfl_down_sync(0xFFFFFFFFu, s, off);
        if (lane == 0) fin[rowi] = s;
    }
    __syncthreads();

    if (threadIdx.x == 0) {
        float invT = 1.0f / (float)T;
        float loss = 0.0f;
#pragma unroll
        for (int e = 0; e < NE; e++)
            loss += (fin[e] * invT) * (fin[NE + e] * invT);
        out[0] = 0.02f * 8.0f * loss;
    }
}

extern "C" void kernel_launch(void* const* d_in, const int* in_sizes, int n_in,
                              void* d_out, int out_size)
{
    const float* logits = (const float*)d_in[0];
    long long T = (long long)in_sizes[0] / NE;
    float* out = (float*)d_out;

    router_fused_kernel<<<GRID, BLOCK>>>(logits, out, T);
}